// round 14
// baseline (speedup 1.0000x reference)
#include <cuda_runtime.h>
#include <cstdint>

// Problem constants (match reference_code)
#define N_ROWS 1000000
#define M_ROWS 2000000
#define DIM    128

// CSR-style row offsets: offsets[r] = lower_bound(sorted_indices, r).
// Segment for output row n = [offsets[n], offsets[n+1]).
// Every entry is written by build_offsets_kernel -> no zero-init needed.
__device__ int g_offsets[N_ROWS + 1];

// ---------------------------------------------------------------------------
// Kernel 1: build the full offsets array from the sorted int32 index array.
// Thread m (0..M inclusive):
//   m == 0      : offsets[r] = 0 for r in [0, idx[0]]
//   m == M      : offsets[r] = M for r in (idx[M-1], N]
//   else if idx[m] != idx[m-1]: offsets[r] = m for r in (idx[m-1], idx[m]]
// Each offsets entry is written exactly once. idx[m-1] comes from a warp
// shuffle (one idx read per element instead of two).
// ---------------------------------------------------------------------------
__global__ void build_offsets_kernel(const int* __restrict__ idx) {
    int m = blockIdx.x * blockDim.x + threadIdx.x;
    if (m > M_ROWS) return;

    int cur = (m < M_ROWS) ? idx[m] : 0;   // m==M handled separately
    // Neighbor idx[m-1] via shuffle; lane 0 (and m==M) loads it directly.
    int prev = __shfl_up_sync(0xFFFFFFFFu, cur, 1);
    if ((threadIdx.x & 31) == 0 && m > 0) prev = idx[m - 1];
    if (m == M_ROWS) prev = idx[M_ROWS - 1];

    if (m == 0) {
        int first = cur;
        if (first < 0) first = 0;
        if (first > N_ROWS - 1) first = N_ROWS - 1;
        for (int r = 0; r <= first; ++r) g_offsets[r] = 0;
    } else if (m == M_ROWS) {
        int last = prev;
        if (last < 0) last = 0;
        if (last > N_ROWS - 1) last = N_ROWS - 1;
        for (int r = last + 1; r <= N_ROWS; ++r) g_offsets[r] = M_ROWS;
    } else if (cur != prev) {
        if (prev < -1) prev = -1;               // defensive clamps
        if (cur > N_ROWS - 1) cur = N_ROWS - 1;
        for (int r = prev + 1; r <= cur; ++r) g_offsets[r] = m;
    }
}

// ---------------------------------------------------------------------------
// Kernel 2 (R8 winner, 512-thread blocks): one warp per output row, lane owns
// one float4. 16 warps/block -> exactly 4 blocks/SM at 64-warp occupancy,
// fewer block boundaries and a shorter tail wave than 256-thread blocks.
// All big streams use-once: __ldcs / __stcs (evict-first).
// ---------------------------------------------------------------------------
__global__ void __launch_bounds__(512) gather_add_kernel(
    const float* __restrict__ var,
    const float* __restrict__ value,
    float* __restrict__ out)
{
    int warp_id = (blockIdx.x * blockDim.x + threadIdx.x) >> 5;
    if (warp_id >= N_ROWS) return;
    int lane = threadIdx.x & 31;

    const float4* vrow = reinterpret_cast<const float4*>(var + (size_t)warp_id * DIM);
    float4 acc = __ldcs(&vrow[lane]);

    int lo = __ldg(&g_offsets[warp_id]);
    int hi = __ldg(&g_offsets[warp_id + 1]);

    // Average segment length is M/N = 2; unroll by 2 to expose MLP.
    int m = lo;
    for (; m + 1 < hi; m += 2) {
        float4 a = __ldcs(&reinterpret_cast<const float4*>(value + (size_t)m * DIM)[lane]);
        float4 b = __ldcs(&reinterpret_cast<const float4*>(value + (size_t)(m + 1) * DIM)[lane]);
        acc.x += a.x + b.x;
        acc.y += a.y + b.y;
        acc.z += a.z + b.z;
        acc.w += a.w + b.w;
    }
    if (m < hi) {
        float4 a = __ldcs(&reinterpret_cast<const float4*>(value + (size_t)m * DIM)[lane]);
        acc.x += a.x;
        acc.y += a.y;
        acc.z += a.z;
        acc.w += a.w;
    }

    __stcs(&reinterpret_cast<float4*>(out + (size_t)warp_id * DIM)[lane], acc);
}

// ---------------------------------------------------------------------------
// Launch: plain serialized launches (PDL tested in R11/R12: neutral-to-worse).
// ---------------------------------------------------------------------------
extern "C" void kernel_launch(void* const* d_in, const int* in_sizes, int n_in,
                              void* d_out, int out_size) {
    const float* var   = (const float*)d_in[0];   // [N, 128] f32
    const float* value = (const float*)d_in[1];   // [M, 128] f32
    const int*   sidx  = (const int*)d_in[2];     // [M] i32 (JAX x64-off), sorted
    // d_in[3] = pos (unused)
    float* out = (float*)d_out;                   // [N, 128] f32

    {
        int threads = 512;
        int blocks = (M_ROWS + 1 + threads - 1) / threads;  // M+1 threads
        build_offsets_kernel<<<blocks, threads>>>(sidx);
    }
    {
        int threads = 512;                         // 16 warps = 16 rows per block
        int warps_per_block = threads / 32;
        int blocks = (N_ROWS + warps_per_block - 1) / warps_per_block;
        gather_add_kernel<<<blocks, threads>>>(var, value, out);
    }
}

// round 15
// speedup vs baseline: 1.0303x; 1.0303x over previous
#include <cuda_runtime.h>
#include <cstdint>

// Problem constants (match reference_code)
#define N_ROWS 1000000
#define M_ROWS 2000000
#define DIM    128

// CSR-style row offsets: offsets[r] = lower_bound(sorted_indices, r).
// Segment for output row n = [offsets[n], offsets[n+1]).
// Every entry is written by build_offsets_kernel -> no zero-init needed.
__device__ int g_offsets[N_ROWS + 1];

// ---------------------------------------------------------------------------
// Kernel 1: build the full offsets array from the sorted int32 index array.
// Thread m (0..M inclusive):
//   m == 0      : offsets[r] = 0 for r in [0, idx[0]]
//   m == M      : offsets[r] = M for r in (idx[M-1], N]
//   else if idx[m] != idx[m-1]: offsets[r] = m for r in (idx[m-1], idx[m]]
// Each offsets entry is written exactly once. idx[m-1] comes from a warp
// shuffle (one idx read per element instead of two).
// ---------------------------------------------------------------------------
__global__ void build_offsets_kernel(const int* __restrict__ idx) {
    int m = blockIdx.x * blockDim.x + threadIdx.x;
    if (m > M_ROWS) return;

    int cur = (m < M_ROWS) ? idx[m] : 0;   // m==M handled separately
    // Neighbor idx[m-1] via shuffle; lane 0 (and m==M) loads it directly.
    int prev = __shfl_up_sync(0xFFFFFFFFu, cur, 1);
    if ((threadIdx.x & 31) == 0 && m > 0) prev = idx[m - 1];
    if (m == M_ROWS) prev = idx[M_ROWS - 1];

    if (m == 0) {
        int first = cur;
        if (first < 0) first = 0;
        if (first > N_ROWS - 1) first = N_ROWS - 1;
        for (int r = 0; r <= first; ++r) g_offsets[r] = 0;
    } else if (m == M_ROWS) {
        int last = prev;
        if (last < 0) last = 0;
        if (last > N_ROWS - 1) last = N_ROWS - 1;
        for (int r = last + 1; r <= N_ROWS; ++r) g_offsets[r] = M_ROWS;
    } else if (cur != prev) {
        if (prev < -1) prev = -1;               // defensive clamps
        if (cur > N_ROWS - 1) cur = N_ROWS - 1;
        for (int r = prev + 1; r <= cur; ++r) g_offsets[r] = m;
    }
}

// ---------------------------------------------------------------------------
// Kernel 2 — the measured-best config (R8): 256-thread blocks, ONE row per
// warp, each lane owns one float4 (4 columns). Measured 297.4us @ DRAM 85.3%;
// 2-rows/warp, PDL, and 512-thread blocks all measured worse.
// All big streams use-once: __ldcs / __stcs (evict-first).
// ---------------------------------------------------------------------------
__global__ void __launch_bounds__(256) gather_add_kernel(
    const float* __restrict__ var,
    const float* __restrict__ value,
    float* __restrict__ out)
{
    int warp_id = (blockIdx.x * blockDim.x + threadIdx.x) >> 5;
    if (warp_id >= N_ROWS) return;
    int lane = threadIdx.x & 31;

    const float4* vrow = reinterpret_cast<const float4*>(var + (size_t)warp_id * DIM);
    float4 acc = __ldcs(&vrow[lane]);

    int lo = __ldg(&g_offsets[warp_id]);
    int hi = __ldg(&g_offsets[warp_id + 1]);

    // Average segment length is M/N = 2; unroll by 2 to expose MLP.
    int m = lo;
    for (; m + 1 < hi; m += 2) {
        float4 a = __ldcs(&reinterpret_cast<const float4*>(value + (size_t)m * DIM)[lane]);
        float4 b = __ldcs(&reinterpret_cast<const float4*>(value + (size_t)(m + 1) * DIM)[lane]);
        acc.x += a.x + b.x;
        acc.y += a.y + b.y;
        acc.z += a.z + b.z;
        acc.w += a.w + b.w;
    }
    if (m < hi) {
        float4 a = __ldcs(&reinterpret_cast<const float4*>(value + (size_t)m * DIM)[lane]);
        acc.x += a.x;
        acc.y += a.y;
        acc.z += a.z;
        acc.w += a.w;
    }

    __stcs(&reinterpret_cast<float4*>(out + (size_t)warp_id * DIM)[lane], acc);
}

// ---------------------------------------------------------------------------
// Launch: plain serialized launches, 256-thread blocks (measured best).
// PDL variants (R11/R12) and 512-thread blocks (R14) all measured worse.
// ---------------------------------------------------------------------------
extern "C" void kernel_launch(void* const* d_in, const int* in_sizes, int n_in,
                              void* d_out, int out_size) {
    const float* var   = (const float*)d_in[0];   // [N, 128] f32
    const float* value = (const float*)d_in[1];   // [M, 128] f32
    const int*   sidx  = (const int*)d_in[2];     // [M] i32 (JAX x64-off), sorted
    // d_in[3] = pos (unused)
    float* out = (float*)d_out;                   // [N, 128] f32

    {
        int threads = 256;
        int blocks = (M_ROWS + 1 + threads - 1) / threads;  // M+1 threads
        build_offsets_kernel<<<blocks, threads>>>(sidx);
    }
    {
        int threads = 256;                       // 8 warps = 8 rows per block
        int warps_per_block = threads / 32;
        int blocks = (N_ROWS + warps_per_block - 1) / warps_per_block;
        gather_add_kernel<<<blocks, threads>>>(var, value, out);
    }
}

// round 16
// speedup vs baseline: 1.0380x; 1.0075x over previous
#include <cuda_runtime.h>
#include <cstdint>

// Problem constants (match reference_code)
#define N_ROWS 1000000
#define M_ROWS 2000000
#define DIM    128

// CSR-style row offsets: offsets[r] = lower_bound(sorted_indices, r).
// Segment for output row n = [offsets[n], offsets[n+1]).
// Every entry is written by build_offsets_kernel -> no zero-init needed.
__device__ int g_offsets[N_ROWS + 1];

// ---------------------------------------------------------------------------
// Kernel 1: build the full offsets array, vectorized: each thread owns a
// window of 4 consecutive m positions loaded as one int4 (M_ROWS % 4 == 0).
// For each m in the window with idx[m] != idx[m-1], fill
//   offsets[r] = m  for r in (idx[m-1], idx[m]].
// Window-first element's predecessor idx[4t-1] is a scalar load hitting the
// neighbor thread's cache line. Thread t == M/4 handles the tail fill
// (r > idx[M-1]) and t == 0 the head fill (r <= idx[0]).
// Each offsets entry is written exactly once.
// ---------------------------------------------------------------------------
__global__ void build_offsets_kernel(const int* __restrict__ idx) {
    int t = blockIdx.x * blockDim.x + threadIdx.x;
    const int T = M_ROWS / 4;
    if (t > T) return;

    if (t == T) {
        // Tail: offsets[r] = M for r in (idx[M-1], N]
        int last = idx[M_ROWS - 1];
        if (last < 0) last = 0;
        if (last > N_ROWS - 1) last = N_ROWS - 1;
        for (int r = last + 1; r <= N_ROWS; ++r) g_offsets[r] = M_ROWS;
        return;
    }

    int4 v = reinterpret_cast<const int4*>(idx)[t];
    int w[4] = {v.x, v.y, v.z, v.w};
    int m0 = t * 4;

    // Predecessor of the window's first element.
    int prev;
    if (t == 0) {
        // Head: offsets[r] = 0 for r in [0, idx[0]]
        int first = w[0];
        if (first < 0) first = 0;
        if (first > N_ROWS - 1) first = N_ROWS - 1;
        for (int r = 0; r <= first; ++r) g_offsets[r] = 0;
        prev = w[0];
    } else {
        prev = idx[m0 - 1];   // same/adjacent sector as neighbor's int4 load
    }

#pragma unroll
    for (int j = (t == 0 ? 1 : 0); j < 4; ++j) {
        int cur = w[j];
        if (cur != prev) {
            int p = prev, c = cur;
            if (p < -1) p = -1;                 // defensive clamps
            if (c > N_ROWS - 1) c = N_ROWS - 1;
            int m = m0 + j;
            for (int r = p + 1; r <= c; ++r) g_offsets[r] = m;
        }
        prev = cur;
    }
}

// ---------------------------------------------------------------------------
// Kernel 2 — the measured-best config (R8/R15): 256-thread blocks, ONE row
// per warp, each lane owns one float4 (4 columns). Measured 294.8-297.4us @
// DRAM 85-86%; 2-rows/warp, PDL, and 512-thread blocks all measured worse.
// All big streams use-once: __ldcs / __stcs (evict-first).
// ---------------------------------------------------------------------------
__global__ void __launch_bounds__(256) gather_add_kernel(
    const float* __restrict__ var,
    const float* __restrict__ value,
    float* __restrict__ out)
{
    int warp_id = (blockIdx.x * blockDim.x + threadIdx.x) >> 5;
    if (warp_id >= N_ROWS) return;
    int lane = threadIdx.x & 31;

    const float4* vrow = reinterpret_cast<const float4*>(var + (size_t)warp_id * DIM);
    float4 acc = __ldcs(&vrow[lane]);

    int lo = __ldg(&g_offsets[warp_id]);
    int hi = __ldg(&g_offsets[warp_id + 1]);

    // Average segment length is M/N = 2; unroll by 2 to expose MLP.
    int m = lo;
    for (; m + 1 < hi; m += 2) {
        float4 a = __ldcs(&reinterpret_cast<const float4*>(value + (size_t)m * DIM)[lane]);
        float4 b = __ldcs(&reinterpret_cast<const float4*>(value + (size_t)(m + 1) * DIM)[lane]);
        acc.x += a.x + b.x;
        acc.y += a.y + b.y;
        acc.z += a.z + b.z;
        acc.w += a.w + b.w;
    }
    if (m < hi) {
        float4 a = __ldcs(&reinterpret_cast<const float4*>(value + (size_t)m * DIM)[lane]);
        acc.x += a.x;
        acc.y += a.y;
        acc.z += a.z;
        acc.w += a.w;
    }

    __stcs(&reinterpret_cast<float4*>(out + (size_t)warp_id * DIM)[lane], acc);
}

// ---------------------------------------------------------------------------
// Launch: plain serialized launches, 256-thread blocks (measured best).
// PDL variants (R11/R12) and 512-thread blocks (R14) all measured worse.
// ---------------------------------------------------------------------------
extern "C" void kernel_launch(void* const* d_in, const int* in_sizes, int n_in,
                              void* d_out, int out_size) {
    const float* var   = (const float*)d_in[0];   // [N, 128] f32
    const float* value = (const float*)d_in[1];   // [M, 128] f32
    const int*   sidx  = (const int*)d_in[2];     // [M] i32 (JAX x64-off), sorted
    // d_in[3] = pos (unused)
    float* out = (float*)d_out;                   // [N, 128] f32

    {
        int threads = 256;
        int work = M_ROWS / 4 + 1;               // one int4-window per thread + tail
        int blocks = (work + threads - 1) / threads;
        build_offsets_kernel<<<blocks, threads>>>(sidx);
    }
    {
        int threads = 256;                       // 8 warps = 8 rows per block
        int warps_per_block = threads / 32;
        int blocks = (N_ROWS + warps_per_block - 1) / warps_per_block;
        gather_add_kernel<<<blocks, threads>>>(var, value, out);
    }
}

// round 17
// speedup vs baseline: 1.0384x; 1.0004x over previous
#include <cuda_runtime.h>
#include <cstdint>

// Problem constants (match reference_code)
#define N_ROWS 1000000
#define M_ROWS 2000000
#define DIM    128

// CSR-style row offsets: offsets[r] = lower_bound(sorted_indices, r).
// Segment for output row n = [offsets[n], offsets[n+1]).
// Every entry is written by build_offsets_kernel -> no zero-init needed.
__device__ int g_offsets[N_ROWS + 1];

// ---------------------------------------------------------------------------
// Kernel 1: build the full offsets array, vectorized: each thread owns a
// window of 8 consecutive m positions loaded as two int4 (M_ROWS % 8 == 0).
// For each m in the window with idx[m] != idx[m-1], fill
//   offsets[r] = m  for r in (idx[m-1], idx[m]].
// Window-first element's predecessor idx[8t-1] is a scalar load hitting the
// neighbor thread's cache line. Thread t == M/8 handles the tail fill
// (r > idx[M-1]) and t == 0 the head fill (r <= idx[0]).
// Each offsets entry is written exactly once.
// ---------------------------------------------------------------------------
__global__ void build_offsets_kernel(const int* __restrict__ idx) {
    int t = blockIdx.x * blockDim.x + threadIdx.x;
    const int T = M_ROWS / 8;
    if (t > T) return;

    if (t == T) {
        // Tail: offsets[r] = M for r in (idx[M-1], N]
        int last = idx[M_ROWS - 1];
        if (last < 0) last = 0;
        if (last > N_ROWS - 1) last = N_ROWS - 1;
        for (int r = last + 1; r <= N_ROWS; ++r) g_offsets[r] = M_ROWS;
        return;
    }

    const int4* vidx = reinterpret_cast<const int4*>(idx);
    int4 v0 = vidx[t * 2];
    int4 v1 = vidx[t * 2 + 1];
    int w[8] = {v0.x, v0.y, v0.z, v0.w, v1.x, v1.y, v1.z, v1.w};
    int m0 = t * 8;

    // Predecessor of the window's first element.
    int prev;
    if (t == 0) {
        // Head: offsets[r] = 0 for r in [0, idx[0]]
        int first = w[0];
        if (first < 0) first = 0;
        if (first > N_ROWS - 1) first = N_ROWS - 1;
        for (int r = 0; r <= first; ++r) g_offsets[r] = 0;
        prev = w[0];
    } else {
        prev = idx[m0 - 1];   // same/adjacent sector as neighbor's int4 load
    }

#pragma unroll
    for (int j = 0; j < 8; ++j) {
        if (t == 0 && j == 0) continue;   // head already handled
        int cur = w[j];
        if (cur != prev) {
            int p = prev, c = cur;
            if (p < -1) p = -1;                 // defensive clamps
            if (c > N_ROWS - 1) c = N_ROWS - 1;
            int m = m0 + j;
            for (int r = p + 1; r <= c; ++r) g_offsets[r] = m;
        }
        prev = cur;
    }
}

// ---------------------------------------------------------------------------
// Kernel 2 — the measured-best config (R8/R15/R16): 256-thread blocks, ONE
// row per warp, each lane owns one float4 (4 columns). Measured
// 294.8-297.4us @ DRAM 85-86% across five rounds; 2-rows/warp, PDL, and
// 512-thread blocks all measured worse.
// All big streams use-once: __ldcs / __stcs (evict-first).
// ---------------------------------------------------------------------------
__global__ void __launch_bounds__(256) gather_add_kernel(
    const float* __restrict__ var,
    const float* __restrict__ value,
    float* __restrict__ out)
{
    int warp_id = (blockIdx.x * blockDim.x + threadIdx.x) >> 5;
    if (warp_id >= N_ROWS) return;
    int lane = threadIdx.x & 31;

    const float4* vrow = reinterpret_cast<const float4*>(var + (size_t)warp_id * DIM);
    float4 acc = __ldcs(&vrow[lane]);

    int lo = __ldg(&g_offsets[warp_id]);
    int hi = __ldg(&g_offsets[warp_id + 1]);

    // Average segment length is M/N = 2; unroll by 2 to expose MLP.
    int m = lo;
    for (; m + 1 < hi; m += 2) {
        float4 a = __ldcs(&reinterpret_cast<const float4*>(value + (size_t)m * DIM)[lane]);
        float4 b = __ldcs(&reinterpret_cast<const float4*>(value + (size_t)(m + 1) * DIM)[lane]);
        acc.x += a.x + b.x;
        acc.y += a.y + b.y;
        acc.z += a.z + b.z;
        acc.w += a.w + b.w;
    }
    if (m < hi) {
        float4 a = __ldcs(&reinterpret_cast<const float4*>(value + (size_t)m * DIM)[lane]);
        acc.x += a.x;
        acc.y += a.y;
        acc.z += a.z;
        acc.w += a.w;
    }

    __stcs(&reinterpret_cast<float4*>(out + (size_t)warp_id * DIM)[lane], acc);
}

// ---------------------------------------------------------------------------
// Launch: plain serialized launches, 256-thread blocks (measured best).
// PDL variants (R11/R12) and 512-thread blocks (R14) all measured worse.
// ---------------------------------------------------------------------------
extern "C" void kernel_launch(void* const* d_in, const int* in_sizes, int n_in,
                              void* d_out, int out_size) {
    const float* var   = (const float*)d_in[0];   // [N, 128] f32
    const float* value = (const float*)d_in[1];   // [M, 128] f32
    const int*   sidx  = (const int*)d_in[2];     // [M] i32 (JAX x64-off), sorted
    // d_in[3] = pos (unused)
    float* out = (float*)d_out;                   // [N, 128] f32

    {
        int threads = 256;
        int work = M_ROWS / 8 + 1;               // one 8-index window per thread + tail
        int blocks = (work + threads - 1) / threads;
        build_offsets_kernel<<<blocks, threads>>>(sidx);
    }
    {
        int threads = 256;                       // 8 warps = 8 rows per block
        int warps_per_block = threads / 32;
        int blocks = (N_ROWS + warps_per_block - 1) / warps_per_block;
        gather_add_kernel<<<blocks, threads>>>(var, value, out);
    }
}